// round 13
// baseline (speedup 1.0000x reference)
#include <cuda_runtime.h>
#include <cuda_bf16.h>

// Fused preprocessing: rescale(1/255) -> bilinear 1280x960 -> 640x640
// (half-pixel centers) -> normalize -> NHWC->NCHW.
//
// R2 winning schedule with ONE structural variable changed: each block now
// processes 2 output rows (4 input rows = 46KB CONTIGUOUS reads), doubling
// the per-block sequential read run to reduce DRAM read/write turnaround
// and page-miss frequency at the memory controller. Unlike the failed R9
// attempt: staging keeps NT=240 with the row index constant-folded per
// unrolled iteration (no divides, no predicated staging tail), one barrier,
// 23KB smem -> same 8 blocks/SM occupancy as R2.
//
// Structure: vertical scale is exactly 2.0 (frac 0.5 -> plain sum, the 0.5
// folds into the normalize scale). Horizontal 1.5: px group {4t..4t+3}
// uses input cols {6t..6t+5}, fracs {.25,.75,.25,.75}; no clamping needed.

#define IN_H    1280
#define IN_W    960
#define OUT_HW  640
#define ROW_F   (IN_W * 3)     // 2880 floats per input row
#define ROW_F4  (ROW_F / 4)    // 720 float4 per input row
#define NT      240
#define PLANE   (OUT_HW * OUT_HW)
#define NBLK    (16 * OUT_HW / 2)   // 5120 blocks, 2 output rows each

__global__ __launch_bounds__(NT) void preproc_kernel(
    const float* __restrict__ img,   // [16, 1280, 960, 3]
    const float* __restrict__ mean,  // [3]
    const float* __restrict__ stdv,  // [3]
    float* __restrict__ out)         // [16, 3, 640, 640]
{
    __shared__ float s_buf[2][ROW_F];   // two vertically-summed rows, 23 KB
    __shared__ float s_sc[3], s_bi[3];

    const int t = threadIdx.x;
    if (t < 3) {
        const float inv = 1.0f / stdv[t];
        s_sc[t] = (0.5f / 255.0f) * inv;   // vertical 0.5 folded in
        s_bi[t] = -mean[t] * inv;
    }

    const int u  = blockIdx.x;     // 0..5119
    const int bb = u >> 8 >> 0;    // (computed precisely below)
    const int bbb = u / 320;       // batch 0..15
    const int yy  = u - bbb * 320; // row-pair 0..319 (output rows 2yy, 2yy+1)
    (void)bb;

    // ---- stage: 4 contiguous input rows (4yy..4yy+3) -> 2 summed rows ----
    // summed element idx in [0,1440): j<3 -> output-row 0 (input rows
    // 4yy,4yy+1), j>=3 -> output-row 1 (input rows 4yy+2,4yy+3).
    // Row index is a compile-time constant per unrolled j: no divides.
    const float4* __restrict__ base4 =
        (const float4*)(img + (size_t)(bbb * IN_H + 4 * yy) * ROW_F);
    float4* s4 = (float4*)s_buf[0];   // flat [1440]
#pragma unroll
    for (int j = 0; j < 6; ++j) {
        const int idx = t + j * NT;            // 0..1439
        const int row = (j < 3) ? 0 : 1;       // constant-folded
        const int col = idx - row * ROW_F4;    // 0..719
        const float4* p = base4 + (size_t)(2 * row) * ROW_F4 + col;
        const float4 a = __ldcs(p);
        const float4 c = __ldcs(p + ROW_F4);
        float4 m;
        m.x = a.x + c.x;  m.y = a.y + c.y;
        m.z = a.z + c.z;  m.w = a.w + c.w;
        s4[idx] = m;
    }
    __syncthreads();

    // ---- compute: 320 px-group units over 240 threads ----
    // unit g: ri = g/160 (output row), tt = g%160 (px group {4tt..4tt+3}).
    // thread t handles g = t; threads t<80 also handle g = 240 + t.
#pragma unroll
    for (int pass = 0; pass < 2; ++pass) {
        const int g = (pass == 0) ? t : (240 + t);
        if (pass == 1 && t >= 80) break;
        const int ri = g / 160;            // 0 or 1 (pass0: t<160 -> 0)
        const int tt = g - ri * 160;       // 0..159

        float v[18];
        const float2* sp = (const float2*)&s_buf[ri][18 * tt];  // 8B aligned
#pragma unroll
        for (int j = 0; j < 9; ++j) {
            const float2 p = sp[j];
            v[2 * j]     = p.x;
            v[2 * j + 1] = p.y;
        }

        const int y  = 2 * yy + ri;
        const int ob = bbb * 3 * PLANE + y * OUT_HW + 4 * tt;
#pragma unroll
        for (int c = 0; c < 3; ++c) {
            const float a0 = v[c],      a1 = v[3 + c],  a2 = v[6 + c];
            const float a3 = v[9 + c],  a4 = v[12 + c], a5 = v[15 + c];
            float4 o;
            o.x = fmaf(a1 - a0, 0.25f, a0);   // fx = .25
            o.y = fmaf(a2 - a1, 0.75f, a1);   // fx = .75
            o.z = fmaf(a4 - a3, 0.25f, a3);
            o.w = fmaf(a5 - a4, 0.75f, a4);
            const float sc = s_sc[c], bi = s_bi[c];
            o.x = fmaf(o.x, sc, bi);
            o.y = fmaf(o.y, sc, bi);
            o.z = fmaf(o.z, sc, bi);
            o.w = fmaf(o.w, sc, bi);
            __stcs((float4*)&out[ob + c * PLANE], o);
        }
    }
}

extern "C" void kernel_launch(void* const* d_in, const int* in_sizes, int n_in,
                              void* d_out, int out_size) {
    const float* img  = (const float*)d_in[0];
    const float* mean = (const float*)d_in[1];
    const float* stdv = (const float*)d_in[2];
    float* out = (float*)d_out;

    preproc_kernel<<<NBLK, NT>>>(img, mean, stdv, out);
}

// round 15
// speedup vs baseline: 1.0113x; 1.0113x over previous
#include <cuda_runtime.h>
#include <cuda_bf16.h>

// FINAL configuration (best measured bench: 51.136 us, DRAM ~76.6%, occ ~90%).
//
// One-pass fused preprocessing, [16,1280,960,3] f32 -> [16,3,640,640] f32:
// cast+rescale(1/255) -> bilinear resize (half-pixel centers, no antialias)
// -> normalize (mean/std) -> NHWC->NCHW.
//
// Math exploited:
//  * vertical scale is exactly 2.0 -> src_y frac is always 0.5, so output
//    row y is the plain average of input rows 2y and 2y+1.
//  * horizontal scale 1.5 -> px group {4t..4t+3} reads input cols {6t..6t+5}
//    with fracs {.25,.75,.25,.75}; no boundary clamping at these shapes.
//  * rescale + normalize fold to one FMA per channel; the 3 divisions are
//    computed once per block (per-thread rcp would be MUFU-bound).
//
// Schedule (every alternative below was benched and regressed):
//  * one block per (output row, batch): 10240 blocks x 240 threads
//  * stage: float4-coalesced loads of both input rows, averaged in
//    registers, ONE 2880-float averaged row stored to smem (11.5 KB)
//  * single __syncthreads; 32 regs -> ~90% occupancy
//  * compute: 160 threads x 4 px from 18 contiguous smem floats each;
//    one float4 store per channel plane (coalesced STG.128)
//  * measured-and-rejected: persistent grid, cp.async double buffering,
//    warp-autonomous staging, 2-rows-per-block, __ldcs/__stcs hints.

#define IN_H    1280
#define IN_W    960
#define OUT_HW  640
#define ROW_F   (IN_W * 3)     // 2880 floats per input row
#define ROW_F4  (ROW_F / 4)    // 720 float4
#define NT      240            // 720 float4 / 240 threads = 3 staging iters
#define PLANE   (OUT_HW * OUT_HW)

__global__ __launch_bounds__(NT) void preproc_final_kernel(
    const float* __restrict__ img,   // [16, 1280, 960, 3]
    const float* __restrict__ mean,  // [3]
    const float* __restrict__ stdv,  // [3]
    float* __restrict__ out)         // [16, 3, 640, 640]
{
    __shared__ float s_row[ROW_F];      // vertically averaged input row
    __shared__ float s_scale[3];
    __shared__ float s_bias[3];

    const int t = threadIdx.x;
    if (t < 3) {
        const float inv = 1.0f / stdv[t];
        s_scale[t] = (1.0f / 255.0f) * inv;
        s_bias[t]  = -mean[t] * inv;
    }

    const int y = blockIdx.x;   // 0..639
    const int b = blockIdx.y;   // 0..15

    // stage: rows 2y, 2y+1 -> averaged row in smem (float4 coalesced)
    const float4* __restrict__ r0 =
        (const float4*)(img + (size_t)(b * IN_H + 2 * y) * ROW_F);
    const float4* __restrict__ r1 = r0 + ROW_F4;
    float4* s4 = (float4*)s_row;
#pragma unroll
    for (int j = 0; j < 3; ++j) {
        const int idx = t + j * NT;
        float4 a = __ldg(&r0[idx]);
        float4 c = __ldg(&r1[idx]);
        float4 m;
        m.x = 0.5f * (a.x + c.x);
        m.y = 0.5f * (a.y + c.y);
        m.z = 0.5f * (a.z + c.z);
        m.w = 0.5f * (a.w + c.w);
        s4[idx] = m;
    }
    __syncthreads();

    // compute: 4 output px per thread, threads 0..159
    if (t < 160) {
        float v[18];
        const float2* sp = (const float2*)&s_row[18 * t];  // 72B stride, 8B ok
#pragma unroll
        for (int j = 0; j < 9; ++j) {
            float2 p = sp[j];
            v[2 * j]     = p.x;
            v[2 * j + 1] = p.y;
        }

        const int ob = b * 3 * PLANE + y * OUT_HW + 4 * t;
#pragma unroll
        for (int c = 0; c < 3; ++c) {
            const float a0 = v[c],      a1 = v[3 + c],  a2 = v[6 + c];
            const float a3 = v[9 + c],  a4 = v[12 + c], a5 = v[15 + c];
            float4 o;
            o.x = fmaf(a1 - a0, 0.25f, a0);   // x = 4t   (fx = .25)
            o.y = fmaf(a2 - a1, 0.75f, a1);   // x = 4t+1 (fx = .75)
            o.z = fmaf(a4 - a3, 0.25f, a3);   // x = 4t+2
            o.w = fmaf(a5 - a4, 0.75f, a4);   // x = 4t+3
            const float sc = s_scale[c], bi = s_bias[c];
            o.x = fmaf(o.x, sc, bi);
            o.y = fmaf(o.y, sc, bi);
            o.z = fmaf(o.z, sc, bi);
            o.w = fmaf(o.w, sc, bi);
            *(float4*)&out[ob + c * PLANE] = o;
        }
    }
}

extern "C" void kernel_launch(void* const* d_in, const int* in_sizes, int n_in,
                              void* d_out, int out_size) {
    const float* img  = (const float*)d_in[0];
    const float* mean = (const float*)d_in[1];
    const float* stdv = (const float*)d_in[2];
    float* out = (float*)d_out;

    dim3 block(NT, 1, 1);
    dim3 grid(OUT_HW, 16, 1);   // (640 rows, 16 batches)
    preproc_final_kernel<<<grid, block>>>(img, mean, stdv, out);
}

// round 16
// speedup vs baseline: 1.0163x; 1.0050x over previous
#include <cuda_runtime.h>
#include <cuda_bf16.h>

// FINAL (locked): best-measured configuration.
// Bench: 51.136-51.200 us across 4 runs | kernel ~46 us | DRAM ~76% | occ ~90%
// Aggregate 314.5 MB compulsory traffic at ~6.8 TB/s kernel-level — the
// practical HBM ceiling for a 3:1 interleaved read/write stream on this part.
//
// One-pass fused preprocessing, [16,1280,960,3] f32 -> [16,3,640,640] f32:
// cast+rescale(1/255) -> bilinear resize (half-pixel centers, no antialias)
// -> normalize (mean/std) -> NHWC->NCHW.
//
// Math exploited:
//  * vertical scale exactly 2.0 -> frac always 0.5: output row y is the
//    plain average of input rows 2y, 2y+1 (averaged once during staging).
//  * horizontal scale 1.5 -> px group {4t..4t+3} reads input cols {6t..6t+5}
//    (disjoint across threads) with fracs {.25,.75,.25,.75}; no clamping.
//  * rescale+normalize fold to one FMA per channel; 3 divides per block.
//
// Schedule (alternatives benched and rejected: persistent grid, cp.async
// double-buffering, register pipelining, warp-autonomous staging,
// 2-rows-per-block, __ldcs/__stcs hints, all regressed or neutral):
//  * one block per (output row, batch): 10240 blocks x 240 threads
//  * stage: float4-coalesced loads of both input rows, averaged in
//    registers, one 2880-float row to smem (11.5 KB); single __syncthreads
//  * compute: 160 threads x 4 px from 18 contiguous smem floats each;
//    one float4 store per channel plane (coalesced STG.128)
//  * 32 regs -> 8 blocks/SM, 60 warps: occupancy-driven latency hiding.

#define IN_H    1280
#define IN_W    960
#define OUT_HW  640
#define ROW_F   (IN_W * 3)     // 2880 floats per input row
#define ROW_F4  (ROW_F / 4)    // 720 float4
#define NT      240            // 720 float4 / 240 threads = 3 staging iters
#define PLANE   (OUT_HW * OUT_HW)

__global__ __launch_bounds__(NT) void preproc_final_kernel(
    const float* __restrict__ img,   // [16, 1280, 960, 3]
    const float* __restrict__ mean,  // [3]
    const float* __restrict__ stdv,  // [3]
    float* __restrict__ out)         // [16, 3, 640, 640]
{
    __shared__ float s_row[ROW_F];      // vertically averaged input row
    __shared__ float s_scale[3];
    __shared__ float s_bias[3];

    const int t = threadIdx.x;
    if (t < 3) {
        const float inv = 1.0f / stdv[t];
        s_scale[t] = (1.0f / 255.0f) * inv;
        s_bias[t]  = -mean[t] * inv;
    }

    const int y = blockIdx.x;   // 0..639
    const int b = blockIdx.y;   // 0..15

    // stage: rows 2y, 2y+1 -> averaged row in smem (float4 coalesced)
    const float4* __restrict__ r0 =
        (const float4*)(img + (size_t)(b * IN_H + 2 * y) * ROW_F);
    const float4* __restrict__ r1 = r0 + ROW_F4;
    float4* s4 = (float4*)s_row;
#pragma unroll
    for (int j = 0; j < 3; ++j) {
        const int idx = t + j * NT;
        float4 a = __ldg(&r0[idx]);
        float4 c = __ldg(&r1[idx]);
        float4 m;
        m.x = 0.5f * (a.x + c.x);
        m.y = 0.5f * (a.y + c.y);
        m.z = 0.5f * (a.z + c.z);
        m.w = 0.5f * (a.w + c.w);
        s4[idx] = m;
    }
    __syncthreads();

    // compute: 4 output px per thread, threads 0..159
    if (t < 160) {
        float v[18];
        const float2* sp = (const float2*)&s_row[18 * t];  // 72B stride, 8B ok
#pragma unroll
        for (int j = 0; j < 9; ++j) {
            float2 p = sp[j];
            v[2 * j]     = p.x;
            v[2 * j + 1] = p.y;
        }

        const int ob = b * 3 * PLANE + y * OUT_HW + 4 * t;
#pragma unroll
        for (int c = 0; c < 3; ++c) {
            const float a0 = v[c],      a1 = v[3 + c],  a2 = v[6 + c];
            const float a3 = v[9 + c],  a4 = v[12 + c], a5 = v[15 + c];
            float4 o;
            o.x = fmaf(a1 - a0, 0.25f, a0);   // x = 4t   (fx = .25)
            o.y = fmaf(a2 - a1, 0.75f, a1);   // x = 4t+1 (fx = .75)
            o.z = fmaf(a4 - a3, 0.25f, a3);   // x = 4t+2
            o.w = fmaf(a5 - a4, 0.75f, a4);   // x = 4t+3
            const float sc = s_scale[c], bi = s_bias[c];
            o.x = fmaf(o.x, sc, bi);
            o.y = fmaf(o.y, sc, bi);
            o.z = fmaf(o.z, sc, bi);
            o.w = fmaf(o.w, sc, bi);
            *(float4*)&out[ob + c * PLANE] = o;
        }
    }
}

extern "C" void kernel_launch(void* const* d_in, const int* in_sizes, int n_in,
                              void* d_out, int out_size) {
    const float* img  = (const float*)d_in[0];
    const float* mean = (const float*)d_in[1];
    const float* stdv = (const float*)d_in[2];
    float* out = (float*)d_out;

    dim3 block(NT, 1, 1);
    dim3 grid(OUT_HW, 16, 1);   // (640 rows, 16 batches)
    preproc_final_kernel<<<grid, block>>>(img, mean, stdv, out);
}